// round 11
// baseline (speedup 1.0000x reference)
#include <cuda_runtime.h>
#include <cuda_fp16.h>
#include <cstdint>

// ---------------------------------------------------------------------------
// Problem constants
// ---------------------------------------------------------------------------
#define NROWS 32768            // 64*512
#define KC    1024             // num centers
#define DDIM  256              // latent dim
#define BM    128              // CTA rows; CTA owns ALL 1024 output cols
#define BN    128              // column block
#define NCB   (KC / BN)        // 8 column blocks
#define NTHR  256              // 8 warps: 2 along M x 4 along N, tile 64x32

// smem: A resident (4 slabs x 128 rows x 64 fp16), B 2 stages same shape
#define SLAB  16384            // 128 rows * 64 fp16 * 2B (128B rows)
#define A_BYTES (4 * SLAB)     // 65536
#define B_STAGE (4 * SLAB)     // 65536
#define SMEM_SZ (A_BYTES + 2 * B_STAGE)   // 196608

// ---------------------------------------------------------------------------
// Device-global scratch
// ---------------------------------------------------------------------------
__device__ __half g_zh[(size_t)NROWS * DDIM];   // fp16 z   (16 MB)
__device__ __half g_ch[(size_t)KC * DDIM];      // fp16 c   (0.5 MB)
__device__ float  g_zsq[NROWS];
__device__ float  g_csq[KC];

// ---------------------------------------------------------------------------
// helpers (sm_80-era PTX only — plain sm_100 target)
// ---------------------------------------------------------------------------
__device__ __forceinline__ uint32_t smem_u32(const void* p) {
    uint32_t a;
    asm("{ .reg .u64 t; cvta.to.shared.u64 t, %1; cvt.u32.u64 %0, t; }"
        : "=r"(a) : "l"(p));
    return a;
}
__device__ __forceinline__ void cpasync16(uint32_t dst, const void* src) {
    asm volatile("cp.async.cg.shared.global [%0], [%1], 16;"
                 :: "r"(dst), "l"(src));
}
__device__ __forceinline__ void ldsm4(uint32_t addr, uint32_t* d) {
    asm volatile("ldmatrix.sync.aligned.m8n8.x4.shared.b16 {%0,%1,%2,%3}, [%4];"
                 : "=r"(d[0]), "=r"(d[1]), "=r"(d[2]), "=r"(d[3])
                 : "r"(addr));
}
__device__ __forceinline__ void mma_f16(float* c, const uint32_t* a,
                                        uint32_t b0, uint32_t b1) {
    asm volatile(
        "mma.sync.aligned.m16n8k16.row.col.f32.f16.f16.f32 "
        "{%0,%1,%2,%3}, {%4,%5,%6,%7}, {%8,%9}, {%0,%1,%2,%3};"
        : "+f"(c[0]), "+f"(c[1]), "+f"(c[2]), "+f"(c[3])
        : "r"(a[0]), "r"(a[1]), "r"(a[2]), "r"(a[3]), "r"(b0), "r"(b1));
}

// ---------------------------------------------------------------------------
// Kernel 1: prep — squared row norms + fp16 conversion (one warp per row)
// ---------------------------------------------------------------------------
__global__ void prep_kernel(const float* __restrict__ z,
                            const float* __restrict__ c) {
    int gw   = (blockIdx.x * blockDim.x + threadIdx.x) >> 5;
    int lane = threadIdx.x & 31;
    if (gw >= NROWS + KC) return;

    const float* src;
    __half*      dst;
    if (gw < NROWS) { src = z + (size_t)gw * DDIM;           dst = g_zh + (size_t)gw * DDIM; }
    else            { src = c + (size_t)(gw - NROWS) * DDIM; dst = g_ch + (size_t)(gw - NROWS) * DDIM; }

    const float4* s4 = (const float4*)src;
    uint2*        d2 = (uint2*)dst;
    float s = 0.0f;
    #pragma unroll
    for (int i = 0; i < 2; i++) {
        float4 v = s4[lane + 32 * i];
        s += v.x * v.x + v.y * v.y + v.z * v.z + v.w * v.w;
        __half2 lo = __floats2half2_rn(v.x, v.y);
        __half2 hi = __floats2half2_rn(v.z, v.w);
        uint2 o;
        o.x = *(uint32_t*)&lo;
        o.y = *(uint32_t*)&hi;
        d2[lane + 32 * i] = o;
    }
    #pragma unroll
    for (int o = 16; o > 0; o >>= 1) s += __shfl_down_sync(0xffffffffu, s, o);
    if (lane == 0) {
        if (gw < NROWS) g_zsq[gw] = s;
        else            g_csq[gw - NROWS] = s;
    }
}

// ---------------------------------------------------------------------------
// Kernel 2: resident-A FP16 GEMM + Student-t + in-CTA normalization
// grid = 256 CTAs, 256 threads (8 warps: 2M x 4N), warp tile 64x32
// mainloop: 8 column blocks; B double-buffered; 2 barriers per block
// ---------------------------------------------------------------------------
__global__ void __launch_bounds__(NTHR, 1)
gemm_kernel(float* __restrict__ out) {
    extern __shared__ __align__(16) char smem[];
    uint32_t sb = smem_u32(smem);
    const uint32_t A0 = sb;
    const uint32_t B0 = sb + A_BYTES;

    int tid  = threadIdx.x;
    int wid  = tid >> 5;
    int lane = tid & 31;
    int gr0  = blockIdx.x * BM;
    int wm   = (wid & 1) * 64;          // warp M offset (2 warps along M)
    int wn   = (wid >> 1) * 32;         // warp N offset (4 warps along N)
    int wnid = wid >> 1;

    // ---- A loader (once): 4096 x 16B / 256 threads ----
    {
        #pragma unroll
        for (int u = 0; u < 16; u++) {
            int f = u * NTHR + tid;
            int slab = f >> 10, rr = (f >> 3) & 127, c4 = f & 7;
            cpasync16(A0 + slab * SLAB + rr * 128 + 16 * (c4 ^ (rr & 7)),
                      g_zh + (size_t)(gr0 + rr) * DDIM + slab * 64 + c4 * 8);
        }
        asm volatile("cp.async.commit_group;");
    }

    // ---- B loader: col block cb -> stage cb&1 (4 slabs) ----
    auto load_B = [&](int cb) {
        uint32_t bb = B0 + (cb & 1) * B_STAGE;
        const __half* gB = g_ch + (size_t)(cb * BN) * DDIM;
        #pragma unroll
        for (int u = 0; u < 16; u++) {
            int f = u * NTHR + tid;
            int slab = f >> 10, rr = (f >> 3) & 127, c4 = f & 7;
            cpasync16(bb + slab * SLAB + rr * 128 + 16 * (c4 ^ (rr & 7)),
                      gB + (size_t)rr * DDIM + slab * 64 + c4 * 8);
        }
        asm volatile("cp.async.commit_group;");
    };
    load_B(0);
    load_B(1);

    // ---- ldmatrix address precompute ----
    // one ldsm.x4 per 16x16 tile: g = matrix idx (0-3), r = row within 8
    int g = lane >> 3, r = lane & 7;
    uint32_t aOff[4], aSw[4];
    #pragma unroll
    for (int ms = 0; ms < 4; ms++) {
        int row = wm + ms * 16 + (g & 1) * 8 + r;
        aOff[ms] = (uint32_t)row * 128;
        aSw[ms]  = (uint32_t)(row & 7);
    }
    uint32_t aDu = (uint32_t)(g >> 1);
    uint32_t bOff[2], bSw[2];
    #pragma unroll
    for (int nj = 0; nj < 2; nj++) {
        int row = wn + nj * 16 + (g >> 1) * 8 + r;
        bOff[nj] = (uint32_t)row * 128;
        bSw[nj]  = (uint32_t)(row & 7);
    }
    uint32_t bDu = (uint32_t)(g & 1);

    float acc[4][4][4];                  // [ms][ns][quad]
    #pragma unroll
    for (int ms = 0; ms < 4; ms++)
        #pragma unroll
        for (int ns = 0; ns < 4; ns++)
            #pragma unroll
            for (int q = 0; q < 4; q++) acc[ms][ns][q] = 0.0f;

    int tig = lane & 3, gid = lane >> 2;
    float rs[4][2];
    #pragma unroll
    for (int ms = 0; ms < 4; ms++) { rs[ms][0] = 0.f; rs[ms][1] = 0.f; }

    // ---- mainloop over 8 column blocks ----
    #pragma unroll 1
    for (int cb = 0; cb < NCB; cb++) {
        asm volatile("cp.async.wait_group 1;");    // B(cb) (and A) landed
        __syncthreads();

        uint32_t bstage = B0 + (cb & 1) * B_STAGE;
        // unbroken run: 4 slabs x 4 k16 steps; 6 LDSM + 16 HMMA per step
        #pragma unroll
        for (int slab = 0; slab < 4; slab++) {
            uint32_t ab = A0 + slab * SLAB;
            uint32_t bb = bstage + slab * SLAB;
            #pragma unroll
            for (int kk = 0; kk < 4; kk++) {
                uint32_t afr[4][4], bfr[2][4];
                #pragma unroll
                for (int ms = 0; ms < 4; ms++)
                    ldsm4(ab + aOff[ms] + 16 * ((2 * kk + aDu) ^ aSw[ms]), afr[ms]);
                #pragma unroll
                for (int nj = 0; nj < 2; nj++)
                    ldsm4(bb + bOff[nj] + 16 * ((2 * kk + bDu) ^ bSw[nj]), bfr[nj]);
                #pragma unroll
                for (int ms = 0; ms < 4; ms++)
                    #pragma unroll
                    for (int ns = 0; ns < 4; ns++)
                        mma_f16(acc[ms][ns], afr[ms],
                                bfr[ns >> 1][(ns & 1) * 2],
                                bfr[ns >> 1][(ns & 1) * 2 + 1]);
            }
        }
        __syncthreads();                           // stage cb&1 free

        if (cb + 2 < NCB) load_B(cb + 2);          // refill freed stage
        else              asm volatile("cp.async.commit_group;");

        // ---- epilogue for this column block (overlaps B load) ----
        #pragma unroll
        for (int ms = 0; ms < 4; ms++) {
            int r0 = gr0 + wm + 16 * ms + gid;
            float zs0 = g_zsq[r0];
            float zs1 = g_zsq[r0 + 8];
            #pragma unroll
            for (int ns = 0; ns < 4; ns++) {
                int col = cb * BN + wn + 8 * ns + 2 * tig;
                float cs0 = __ldg(&g_csq[col]);
                float cs1 = __ldg(&g_csq[col + 1]);
                float d00 = fmaxf(fmaf(-2.0f, acc[ms][ns][0], zs0 + cs0), 0.0f);
                float d01 = fmaxf(fmaf(-2.0f, acc[ms][ns][1], zs0 + cs1), 0.0f);
                float d10 = fmaxf(fmaf(-2.0f, acc[ms][ns][2], zs1 + cs0), 0.0f);
                float d11 = fmaxf(fmaf(-2.0f, acc[ms][ns][3], zs1 + cs1), 0.0f);
                float s00, s01, s10, s11;
                { float x = fmaf(d00, 0.1f, 1.0f); float y = rsqrtf(x);
                  float y2 = y*y, y4 = y2*y2, y8 = y4*y4; s00 = y8*y2*y; }
                { float x = fmaf(d01, 0.1f, 1.0f); float y = rsqrtf(x);
                  float y2 = y*y, y4 = y2*y2, y8 = y4*y4; s01 = y8*y2*y; }
                { float x = fmaf(d10, 0.1f, 1.0f); float y = rsqrtf(x);
                  float y2 = y*y, y4 = y2*y2, y8 = y4*y4; s10 = y8*y2*y; }
                { float x = fmaf(d11, 0.1f, 1.0f); float y = rsqrtf(x);
                  float y2 = y*y, y4 = y2*y2, y8 = y4*y4; s11 = y8*y2*y; }
                rs[ms][0] += s00 + s01;
                rs[ms][1] += s10 + s11;
                *(float2*)(out + (size_t)r0 * KC + col)       = make_float2(s00, s01);
                *(float2*)(out + (size_t)(r0 + 8) * KC + col) = make_float2(s10, s11);
                acc[ms][ns][0] = 0.f; acc[ms][ns][1] = 0.f;
                acc[ms][ns][2] = 0.f; acc[ms][ns][3] = 0.f;
            }
        }
    }

    // ---- row-sum reduction: quad -> smem -> inv per row ----
    #pragma unroll
    for (int ms = 0; ms < 4; ms++)
        #pragma unroll
        for (int h = 0; h < 2; h++) {
            float v = rs[ms][h];
            v += __shfl_xor_sync(0xffffffffu, v, 1);
            v += __shfl_xor_sync(0xffffffffu, v, 2);
            rs[ms][h] = v;
        }
    __syncthreads();                  // tiles dead; reuse smem
    float* red = (float*)smem;        // [128 rows][4 warp_n]
    float* inv = red + 512;
    if (tig == 0) {
        #pragma unroll
        for (int ms = 0; ms < 4; ms++)
            #pragma unroll
            for (int h = 0; h < 2; h++)
                red[(wm + 16 * ms + 8 * h + gid) * 4 + wnid] = rs[ms][h];
    }
    __syncthreads();
    if (tid < BM)
        inv[tid] = 1.0f / (red[tid * 4] + red[tid * 4 + 1]
                         + red[tid * 4 + 2] + red[tid * 4 + 3]);
    __syncthreads();

    // ---- in-CTA normalization pass over own 512KB tile (L2-hot) ----
    float4* o4 = (float4*)out + (size_t)gr0 * (KC / 4);
    #pragma unroll 4
    for (int u = 0; u < 128; u++) {
        int idx = u * NTHR + tid;
        float iv = inv[idx >> 8];          // 256 float4 per row
        float4 v = o4[idx];
        v.x *= iv; v.y *= iv; v.z *= iv; v.w *= iv;
        o4[idx] = v;
    }
}

// ---------------------------------------------------------------------------
extern "C" void kernel_launch(void* const* d_in, const int* in_sizes, int n_in,
                              void* d_out, int out_size) {
    const float* z = (const float*)d_in[0];
    const float* c = (const float*)d_in[1];
    if (in_sizes[0] == KC * DDIM) {          // defensive: metadata order
        const float* t = z; z = c; c = t;
    }
    float* out = (float*)d_out;

    static int smem_set = 0;
    if (!smem_set) {
        cudaFuncSetAttribute(gemm_kernel,
                             cudaFuncAttributeMaxDynamicSharedMemorySize, SMEM_SZ);
        smem_set = 1;
    }

    prep_kernel<<<4224, 256>>>(z, c);
    gemm_kernel<<<NROWS / BM, NTHR, SMEM_SZ>>>(out);
}